// round 17
// baseline (speedup 1.0000x reference)
#include <cuda_runtime.h>
#include <cuda_bf16.h>
#include <cstdint>

#define DM 1024
#define DS 16
#define NB 4
#define LS 2048
#define MR (NB*LS)      // 8192 rows
#define LC 32           // scan chunk length
#define NCH (LS/LC)     // 64 chunks
#define NEL (NB*DM*DS)  // 65536 state elements
#define SEGL 8          // chunks per segment
#define NSEG (NCH/SEGL) // 8 segments

// ---------------- scratch (device globals; no allocations) ----------------
__device__ __align__(256) __nv_bfloat16 g_xn[MR*DM];     // layernormed x (bf16)
__device__ __align__(256) __nv_bfloat16 g_w1[2*DM*DM];   // in_w bf16
__device__ __align__(256) __nv_bfloat16 g_w2[DM*DM];     // out_w bf16
__device__ __align__(256) __nv_bfloat16 g_xproj[MR*DM];  // ssm input u
__device__ __align__(256) __nv_bfloat16 g_zs[MR*DM];     // silu(z)
__device__ __align__(256) __nv_bfloat16 g_gated[MR*DM];  // y * silu(z)
__device__ __align__(256) float g_Abar[DM*DS];
__device__ __align__(256) float g_cbdt[DM*DS];
__device__ __align__(256) float g_Apow[DM*DS];           // Abar^LC
__device__ __align__(256) float g_F[NCH*NEL];            // chunk-local end states
__device__ __align__(256) float g_Sin[NCH*NEL];          // chunk incoming (seg-local)
__device__ __align__(256) float g_Seg[NSEG*NEL];         // segment end states
__device__ __align__(256) float g_SegIn[NSEG*NEL];       // segment incoming states

// ---------------- PTX helpers ----------------
__device__ __forceinline__ void cp16(uint32_t s, const void* g){
    asm volatile("cp.async.cg.shared.global [%0], [%1], 16;\n" :: "r"(s), "l"(g));
}
#define LDSM4(v, addr) \
    asm volatile("ldmatrix.sync.aligned.m8n8.x4.shared.b16 {%0,%1,%2,%3}, [%4];" \
        : "=r"((v)[0]), "=r"((v)[1]), "=r"((v)[2]), "=r"((v)[3]) : "r"(addr))
#define MMA16816(d, a, b0, b1) \
    asm volatile("mma.sync.aligned.m16n8k16.row.col.f32.bf16.bf16.f32 " \
        "{%0,%1,%2,%3},{%4,%5,%6,%7},{%8,%9},{%0,%1,%2,%3};" \
        : "+f"((d)[0]), "+f"((d)[1]), "+f"((d)[2]), "+f"((d)[3]) \
        : "r"((a)[0]), "r"((a)[1]), "r"((a)[2]), "r"((a)[3]), "r"(b0), "r"(b1))

// Blackwell packed 2xf32 FMA (PTX-only; ptxas never auto-fuses)
__device__ __forceinline__ unsigned long long pk2(float lo, float hi){
    unsigned long long r;
    asm("mov.b64 %0, {%1,%2};" : "=l"(r) : "f"(lo), "f"(hi));
    return r;
}
__device__ __forceinline__ void unpk2(unsigned long long v, float& lo, float& hi){
    asm("mov.b64 {%0,%1}, %2;" : "=f"(lo), "=f"(hi) : "l"(v));
}
#define FMA2(d, a, b, c) \
    asm("fma.rn.f32x2 %0, %1, %2, %3;" : "=l"(d) : "l"(a), "l"(b), "l"(c))

// ---------------- prep: weight bf16 cast (vectorized) + SSM params ----------
__global__ void prep_kernel(const float* __restrict__ in_w, const float* __restrict__ out_w,
                            const float* __restrict__ A_log, const float* __restrict__ Bp,
                            const float* __restrict__ Cp, const float* __restrict__ log_dt){
    const int n1 = 2*DM*DM/4, n2 = DM*DM/4, n3 = DM*DS;
    int stride = gridDim.x*blockDim.x;
    for(int i = blockIdx.x*blockDim.x + threadIdx.x; i < n1 + n2 + n3; i += stride){
        if(i < n1 + n2){
            const float* src = (i < n1) ? in_w : out_w;
            int j = (i < n1) ? i : i - n1;
            float4 v = reinterpret_cast<const float4*>(src)[j];
            __nv_bfloat162 p0 = __floats2bfloat162_rn(v.x, v.y);
            __nv_bfloat162 p1 = __floats2bfloat162_rn(v.z, v.w);
            uint2 pk; pk.x = *(uint32_t*)&p0; pk.y = *(uint32_t*)&p1;
            if(i < n1) reinterpret_cast<uint2*>(g_w1)[j] = pk;
            else       reinterpret_cast<uint2*>(g_w2)[j] = pk;
        } else {
            int j = i - n1 - n2;                  // over DM*DS
            int d = j >> 4;
            float dt = fminf(fmaxf(expf(log_dt[d]), 1e-4f), 1.0f);
            float Ab = expf(-expf(A_log[j]) * dt);
            Ab = fminf(fmaxf(Ab, 1e-8f), 1.0f - 1e-8f);
            g_Abar[j] = Ab;
            g_cbdt[j] = Cp[j] * Bp[j] * dt;
            float p = Ab;
            #pragma unroll
            for(int q = 0; q < 5; q++) p = p*p;   // Abar^32 (LC=32)
            g_Apow[j] = p;
        }
    }
}

// ---------------- layernorm (row = one block) ----------------
__global__ void ln_kernel(const float* __restrict__ x, const float* __restrict__ g,
                          const float* __restrict__ b){
    int r = blockIdx.x, t = threadIdx.x;
    float4 v = reinterpret_cast<const float4*>(x + (size_t)r*DM)[t];
    float s = v.x+v.y+v.z+v.w;
    float q = v.x*v.x + v.y*v.y + v.z*v.z + v.w*v.w;
    #pragma unroll
    for(int o = 16; o; o >>= 1){
        s += __shfl_xor_sync(0xffffffffu, s, o);
        q += __shfl_xor_sync(0xffffffffu, q, o);
    }
    __shared__ float ss[8], qs[8];
    int w = t >> 5, lane = t & 31;
    if(lane == 0){ ss[w] = s; qs[w] = q; }
    __syncthreads();
    s = 0.f; q = 0.f;
    #pragma unroll
    for(int i = 0; i < 8; i++){ s += ss[i]; q += qs[i]; }
    float mu  = s * (1.0f/DM);
    float var = q * (1.0f/DM) - mu*mu;
    float rs  = rsqrtf(var + 1e-5f);
    float4 gv = reinterpret_cast<const float4*>(g)[t];
    float4 bv = reinterpret_cast<const float4*>(b)[t];
    float o0 = (v.x-mu)*rs*gv.x + bv.x;
    float o1 = (v.y-mu)*rs*gv.y + bv.y;
    float o2 = (v.z-mu)*rs*gv.z + bv.z;
    float o3 = (v.w-mu)*rs*gv.w + bv.w;
    __nv_bfloat162 p0 = __floats2bfloat162_rn(o0, o1);
    __nv_bfloat162 p1 = __floats2bfloat162_rn(o2, o3);
    uint2 pk; pk.x = *(uint32_t*)&p0; pk.y = *(uint32_t*)&p1;
    reinterpret_cast<uint2*>(g_xn + (size_t)r*DM)[t] = pk;
}

// ---------------- HMMA GEMM: 128x128 tile, K=64 stages, 3-stage pipeline -----
// Epilogue stages f32 tile in smem (pitch 136 floats) -> coalesced stores.
// MODE 0 x-half additionally computes the 4 chunk-end scan states (fused pass1,
// f32x2-packed FMAs).
#define STG_BYTES 32768
#define NSTG 3
#define EPI_PITCH 136
#define GEMM_SMEM (NSTG*STG_BYTES + 128)     // 98432; epilogue needs 128*136*4=69632

template<int MODE>
__global__ void __launch_bounds__(256, 2) gemm_hmma(const float* __restrict__ bias,
                                                    const float* __restrict__ resid,
                                                    float* __restrict__ outp){
    constexpr int K = DM, KB = K*2;
    const __nv_bfloat16* __restrict__ Am = (MODE==0) ? g_xn : g_gated;
    const __nv_bfloat16* __restrict__ Bm = (MODE==0) ? g_w1 : g_w2;

    extern __shared__ char smem_dyn[];
    uint32_t sraw  = (uint32_t)__cvta_generic_to_shared(smem_dyn);
    uint32_t sbase = (sraw + 127) & ~127u;
    float*   epi   = (float*)(smem_dyn + (sbase - sraw));   // generic view of sbase

    int t = threadIdx.x, lane = t & 31, wid = t >> 5;
    int wm = wid >> 1, wn = wid & 1;             // 4 x 2 warps over 128x128
    int m0 = blockIdx.y * 128, n0 = blockIdx.x * 128;

    // -------- hoisted load addressing: 4 A-chunks + 4 B-chunks per thread ----
    uint32_t soff[4];
    const char* pA[4];
    const char* pB[4];
    #pragma unroll
    for(int i = 0; i < 4; i++){
        int idx = t + i*256;
        int r = idx >> 3, c = idx & 7;
        soff[i] = (uint32_t)(r*128 + ((c ^ (r & 7)) << 4));
        pA[i] = (const char*)Am + (size_t)(m0 + r)*KB + c*16;
        pB[i] = (const char*)Bm + (size_t)(n0 + r)*KB + c*16;
    }

    auto load = [&](uint32_t stg){
        #pragma unroll
        for(int i = 0; i < 4; i++){
            cp16(stg + soff[i],          pA[i]);
            cp16(stg + 16384 + soff[i],  pB[i]);
            pA[i] += 128; pB[i] += 128;
        }
    };

    float acc[2][8][4];
    #pragma unroll
    for(int i=0;i<2;i++)
    #pragma unroll
    for(int j=0;j<8;j++)
    #pragma unroll
    for(int q=0;q<4;q++) acc[i][j][q] = 0.f;

    load(sbase + 0*STG_BYTES); asm volatile("cp.async.commit_group;");
    load(sbase + 1*STG_BYTES); asm volatile("cp.async.commit_group;");

    // -------- hoisted fragment addressing ------------------------------------
    int la_r = lane & 15, la_k = lane >> 4;
    uint32_t sw  = (uint32_t)(la_r & 7);
    uint32_t kx[4];
    #pragma unroll
    for(int kg = 0; kg < 4; kg++)
        kx[kg] = (((uint32_t)(kg*2 + la_k)) ^ sw) << 4;
    uint32_t aoff = (uint32_t)((wm*32 + la_r) * 128);
    uint32_t boff = (uint32_t)((wn*64 + la_r) * 128) + 16384;

    const int NCHK = K/64;                        // 16 chunks
    #pragma unroll 1
    for(int k = 0; k < NCHK; k++){
        uint32_t stg = sbase + (uint32_t)((k % 3) * STG_BYTES);
        asm volatile("cp.async.wait_group 1;");
        __syncthreads();
        if(k + 2 < NCHK) load(sbase + (uint32_t)(((k+2) % 3) * STG_BYTES));
        asm volatile("cp.async.commit_group;");
        uint32_t smA = stg + aoff;
        uint32_t smB = stg + boff;
        #pragma unroll
        for(int kg = 0; kg < 4; kg++){            // 4 x k16 between barriers
            uint32_t kc = kx[kg];
            uint32_t a[2][4], b[4][4];
            #pragma unroll
            for(int mi = 0; mi < 2; mi++) LDSM4(a[mi], smA + mi*2048 + kc);
            #pragma unroll
            for(int ng = 0; ng < 4; ng++) LDSM4(b[ng], smB + ng*2048 + kc);
            #pragma unroll
            for(int mi = 0; mi < 2; mi++)
            #pragma unroll
            for(int ng = 0; ng < 4; ng++){
                MMA16816(acc[mi][2*ng],   a[mi], b[ng][0], b[ng][2]);
                MMA16816(acc[mi][2*ng+1], a[mi], b[ng][1], b[ng][3]);
            }
        }
    }
    asm volatile("cp.async.wait_group 0;");
    __syncthreads();                              // mainloop smem dead; reuse for staging

    // -------- stage f32 tile (with bias, + silu for z-half) ------------------
    int grp = lane >> 2, c2 = (lane & 3) * 2;
    const bool zh = (MODE == 0) && (n0 >= DM);
    #pragma unroll
    for(int mi = 0; mi < 2; mi++){
        #pragma unroll
        for(int ni = 0; ni < 8; ni++){
            int rl = wm*32 + mi*16 + grp;
            int cl = wn*64 + ni*8 + c2;
            float b0 = __ldg(&bias[n0 + cl]), b1 = __ldg(&bias[n0 + cl + 1]);
            #pragma unroll
            for(int h = 0; h < 2; h++){
                float v0 = acc[mi][ni][2*h+0] + b0;
                float v1 = acc[mi][ni][2*h+1] + b1;
                if(zh){
                    v0 = v0 / (1.f + __expf(-v0));
                    v1 = v1 / (1.f + __expf(-v1));
                }
                float2 p; p.x = v0; p.y = v1;
                *(float2*)&epi[(rl + h*8)*EPI_PITCH + cl] = p;
            }
        }
    }
    __syncthreads();

    if(MODE == 0){
        // coalesced bf16 write-out: 128 rows x 16 x 16B
        __nv_bfloat16* dstb = zh ? g_zs : g_xproj;
        int colb = n0 - (zh ? DM : 0);
        #pragma unroll
        for(int i = 0; i < 8; i++){
            int idx = t + i*256;
            int r = idx >> 4, c = idx & 15;
            const float4 f0 = *(const float4*)&epi[r*EPI_PITCH + c*8];
            const float4 f1 = *(const float4*)&epi[r*EPI_PITCH + c*8 + 4];
            __nv_bfloat162 h0 = __floats2bfloat162_rn(f0.x, f0.y);
            __nv_bfloat162 h1 = __floats2bfloat162_rn(f0.z, f0.w);
            __nv_bfloat162 h2 = __floats2bfloat162_rn(f1.x, f1.y);
            __nv_bfloat162 h3 = __floats2bfloat162_rn(f1.z, f1.w);
            uint4 pk; pk.x = *(uint32_t*)&h0; pk.y = *(uint32_t*)&h1;
            pk.z = *(uint32_t*)&h2; pk.w = *(uint32_t*)&h3;
            *(uint4*)&dstb[(size_t)(m0 + r)*DM + colb + c*8] = pk;
        }
        // fused pass1: 4 chunk-end states per column (x-half only), f32x2 FMAs
        if(!zh){
            int bb = m0 >> 11;                    // /LS
            int cbase = (m0 & (LS-1)) >> 5;       // /LC
            #pragma unroll
            for(int task = t; task < 512; task += 256){
                int cc = task >> 7, col = task & 127;
                int d = n0 + col;
                unsigned long long A2[8], S2[8];
                const float4* A4 = reinterpret_cast<const float4*>(g_Abar + d*DS);
                #pragma unroll
                for(int j=0;j<4;j++){
                    float4 v=A4[j];
                    A2[2*j]   = pk2(v.x, v.y);
                    A2[2*j+1] = pk2(v.z, v.w);
                }
                unsigned long long z2 = pk2(0.f, 0.f);
                #pragma unroll
                for(int n=0;n<8;n++) S2[n] = z2;
                const float* up = &epi[(cc*32)*EPI_PITCH + col];
                #pragma unroll 8
                for(int row = 0; row < LC; ++row){
                    float uv = up[row*EPI_PITCH];
                    unsigned long long uv2 = pk2(uv, uv);
                    #pragma unroll
                    for(int n=0;n<8;n++) FMA2(S2[n], A2[n], S2[n], uv2);
                }
                float4* F4 = reinterpret_cast<float4*>(
                    g_F + (size_t)(((cbase+cc)*NB + bb)*DM + d)*DS);
                #pragma unroll
                for(int j=0;j<4;j++){
                    float4 v;
                    unpk2(S2[2*j],   v.x, v.y);
                    unpk2(S2[2*j+1], v.z, v.w);
                    F4[j]=v;
                }
            }
        }
    } else {
        // coalesced f32 write-out with resid + clip: 128 rows x 32 float4
        #pragma unroll
        for(int i = 0; i < 16; i++){
            int idx = t + i*256;
            int r = idx >> 5, c = idx & 31;
            size_t gi = (size_t)(m0 + r)*DM + n0 + c*4;
            float4 v = *(const float4*)&epi[r*EPI_PITCH + c*4];
            float4 rv = *(const float4*)&resid[gi];
            v.x = fminf(fmaxf(v.x + rv.x, -10.f), 10.f);
            v.y = fminf(fmaxf(v.y + rv.y, -10.f), 10.f);
            v.z = fminf(fmaxf(v.z + rv.z, -10.f), 10.f);
            v.w = fminf(fmaxf(v.w + rv.w, -10.f), 10.f);
            *(float4*)&outp[gi] = v;
        }
    }
}

// ---------------- SSM two-level chunk scan ----------------
// pass2a: segment-local scans (preloaded F, register prefix).
__global__ void ssm_pass2a(){
    int t = threadIdx.x;
    int seg = blockIdx.x >> 8;                      // 8 segments x 256 blocks
    int i = ((blockIdx.x & 255) << 8) + t;          // element 0..NEL-1
    float Ap = g_Apow[i & (DM*DS - 1)];
    float f[SEGL];
    #pragma unroll
    for(int j = 0; j < SEGL; j++)
        f[j] = g_F[(size_t)(seg*SEGL + j)*NEL + i]; // 8 independent loads
    float s = 0.f;
    #pragma unroll
    for(int j = 0; j < SEGL; j++){
        g_Sin[(size_t)(seg*SEGL + j)*NEL + i] = s;  // segment-LOCAL incoming
        s = fmaf(Ap, s, f[j]);
    }
    g_Seg[(size_t)seg*NEL + i] = s;                 // segment end-state (zero init)
}

// pass2b: scan the 8 segment totals with decay Apow^SEGL (preloaded).
__global__ void ssm_pass2b(){
    int i = blockIdx.x*blockDim.x + threadIdx.x;
    float Ap = g_Apow[i & (DM*DS - 1)];
    float p2 = Ap*Ap, p4 = p2*p2, Ap8 = p4*p4;      // Apow^8
    float f[NSEG];
    #pragma unroll
    for(int seg = 0; seg < NSEG; seg++)
        f[seg] = g_Seg[(size_t)seg*NEL + i];        // 8 independent loads
    float s = 0.f;
    #pragma unroll
    for(int seg = 0; seg < NSEG; seg++){
        g_SegIn[(size_t)seg*NEL + i] = s;
        s = fmaf(Ap8, s, f[seg]);
    }
}

// pass3: replay chunk with true incoming state = local + Apow^j * SegIn.
// Inner loop uses f32x2 packed FMAs (states + output dot).
__global__ void ssm_pass3(){
    __shared__ __align__(16) __nv_bfloat16 su[LC*128];   // 8KB u
    __shared__ __align__(16) __nv_bfloat16 sz[LC*128];   // 8KB silu(z)
    __shared__ __align__(16) __nv_bfloat16 so[LC*128];   // 8KB out
    int t = threadIdx.x;
    int c = blockIdx.y, b = blockIdx.z;
    int d = blockIdx.x*128 + t;
    size_t goff = (size_t)(b*LS + c*LC)*DM + blockIdx.x*128;
    const char* gu = (const char*)(g_xproj + goff);
    const char* gz = (const char*)(g_zs + goff);
    uint32_t sbu = (uint32_t)__cvta_generic_to_shared(su);
    uint32_t sbz = (uint32_t)__cvta_generic_to_shared(sz);
    #pragma unroll
    for(int i = 0; i < 4; i++){
        int idx = t + i*128;
        size_t go = (size_t)(idx >> 4)*(DM*2) + (idx & 15)*16;
        cp16(sbu + (uint32_t)idx*16, gu + go);
        cp16(sbz + (uint32_t)idx*16, gz + go);
    }
    asm volatile("cp.async.commit_group;");

    int seg = c >> 3, jj = c & 7;
    size_t eoff = (size_t)(b*DM + d)*DS;
    unsigned long long A2[8], CB2[8], S2[8];
    const float4* A4 = reinterpret_cast<const float4*>(g_Abar + d*DS);
    const float4* C4 = reinterpret_cast<const float4*>(g_cbdt + d*DS);
    const float4* P4 = reinterpret_cast<const float4*>(g_Apow + d*DS);
    const float4* S4 = reinterpret_cast<const float4*>(g_Sin   + (size_t)c*NEL   + eoff);
    const float4* G4 = reinterpret_cast<const float4*>(g_SegIn + (size_t)seg*NEL + eoff);
    #pragma unroll
    for(int j=0;j<4;j++){
        float4 va=A4[j];
        A2[2*j]   = pk2(va.x, va.y);
        A2[2*j+1] = pk2(va.z, va.w);
        float4 vc=C4[j];
        CB2[2*j]   = pk2(vc.x, vc.y);
        CB2[2*j+1] = pk2(vc.z, vc.w);
        float4 vs=S4[j]; float4 vg=G4[j]; float4 vp=P4[j];
        float pw[4] = {vp.x, vp.y, vp.z, vp.w};
        float loc[4] = {vs.x, vs.y, vs.z, vs.w};
        float gin[4] = {vg.x, vg.y, vg.z, vg.w};
        float sv[4];
        #pragma unroll
        for(int q=0;q<4;q++){
            float p1 = pw[q], p2 = p1*p1, p4v = p2*p2;
            float apj = 1.f;
            if(jj & 1) apj *= p1;
            if(jj & 2) apj *= p2;
            if(jj & 4) apj *= p4v;
            sv[q] = fmaf(apj, gin[q], loc[q]);
        }
        S2[2*j]   = pk2(sv[0], sv[1]);
        S2[2*j+1] = pk2(sv[2], sv[3]);
    }
    unsigned long long z2 = pk2(0.f, 0.f);
    asm volatile("cp.async.wait_group 0;");
    __syncthreads();
    #pragma unroll 4
    for(int tt = 0; tt < LC; ++tt){
        float uv = __bfloat162float(su[tt*128 + t]);
        unsigned long long uv2 = pk2(uv, uv);
        #pragma unroll
        for(int n=0;n<8;n++) FMA2(S2[n], A2[n], S2[n], uv2);
        unsigned long long acc2 = z2;
        #pragma unroll
        for(int n=0;n<8;n++) FMA2(acc2, CB2[n], S2[n], acc2);
        float ylo, yhi;
        unpk2(acc2, ylo, yhi);
        float y = ylo + yhi;
        float zv = __bfloat162float(sz[tt*128 + t]);
        so[tt*128 + t] = __float2bfloat16_rn(y * zv);
    }
    __syncthreads();
    char* gg = (char*)(g_gated + goff);
    #pragma unroll
    for(int i = 0; i < 4; i++){                 // coalesced 16B stores
        int idx = t + i*128;
        *reinterpret_cast<uint4*>(gg + (size_t)(idx >> 4)*(DM*2) + (idx & 15)*16)
            = *reinterpret_cast<const uint4*>(reinterpret_cast<const char*>(so) + idx*16);
    }
}

// ---------------- launch ----------------
extern "C" void kernel_launch(void* const* d_in, const int* in_sizes, int n_in,
                              void* d_out, int out_size){
    const float* x      = (const float*)d_in[0];
    const float* A_log  = (const float*)d_in[1];
    const float* Bp     = (const float*)d_in[2];
    const float* Cp     = (const float*)d_in[3];
    const float* log_dt = (const float*)d_in[4];
    const float* in_w   = (const float*)d_in[5];
    const float* in_b   = (const float*)d_in[6];
    const float* out_w  = (const float*)d_in[7];
    const float* out_b  = (const float*)d_in[8];
    const float* ln_g   = (const float*)d_in[9];
    const float* ln_b   = (const float*)d_in[10];
    float* outp = (float*)d_out;

    cudaFuncSetAttribute(gemm_hmma<0>, cudaFuncAttributeMaxDynamicSharedMemorySize, GEMM_SMEM);
    cudaFuncSetAttribute(gemm_hmma<1>, cudaFuncAttributeMaxDynamicSharedMemorySize, GEMM_SMEM);

    prep_kernel<<<512, 256>>>(in_w, out_w, A_log, Bp, Cp, log_dt);
    ln_kernel<<<MR, 256>>>(x, ln_g, ln_b);
    gemm_hmma<0><<<dim3(2*DM/128, MR/128), 256, GEMM_SMEM>>>(in_b, nullptr, nullptr);
    ssm_pass2a<<<NSEG*256, 256>>>();
    ssm_pass2b<<<NEL/256, 256>>>();
    ssm_pass3<<<dim3(DM/128, NCH, NB), 128>>>();
    gemm_hmma<1><<<dim3(DM/128, MR/128), 256, GEMM_SMEM>>>(out_b, x, outp);
}